// round 5
// baseline (speedup 1.0000x reference)
#include <cuda_runtime.h>
#include <cuda_fp16.h>
#include <cstdint>

// ---------------- problem constants ----------------
#define N_    32
#define C_    128
#define H_    56
#define W_    56
#define K_    256
#define HW_   3136
#define PIX_  100352
#define KINP  1152      // 128*9
#define HP_   58
#define WP_   58

// ---------------- GEMM tiling ----------------
#define BM    128       // k-out per CTA
#define BN    128       // pixels per CTA
#define BK    64        // k-halves per stage
#define NSTEP 18        // 1152/64
#define PITCH 72        // halves per smem row (BK + 8) -> conflict-free
#define SA_BYTES (BM * PITCH * 2)               // 18432
#define STAGE_BYTES ((BM + BN) * PITCH * 2)     // 36864
#define SMEM_TOTAL  (3 * STAGE_BYTES)           // 110592

// ---------------- scratch ----------------
__device__ alignas(1024) __half g_xp[(size_t)N_ * HP_ * WP_ * C_];
__device__ alignas(1024) __half g_wq[K_ * KINP];

// ---------------- helpers ----------------
__device__ __forceinline__ uint32_t smem_u32(const void* p) {
    uint32_t a;
    asm("{ .reg .u64 t; cvta.to.shared.u64 t, %1; cvt.u32.u64 %0, t; }" : "=r"(a) : "l"(p));
    return a;
}
#define CP16(dst, src) \
    asm volatile("cp.async.cg.shared.global [%0], [%1], 16;" :: "r"(dst), "l"(src) : "memory")
#define CP_COMMIT() asm volatile("cp.async.commit_group;" ::: "memory")
#define CP_WAIT1()  asm volatile("cp.async.wait_group 1;" ::: "memory")
#define CP_WAIT0()  asm volatile("cp.async.wait_group 0;" ::: "memory")
#define LDSM_X4(r0, r1, r2, r3, addr) \
    asm volatile("ldmatrix.sync.aligned.m8n8.x4.shared.b16 {%0,%1,%2,%3}, [%4];" \
        : "=r"(r0), "=r"(r1), "=r"(r2), "=r"(r3) : "r"(addr))

__device__ __forceinline__ float quant16f(float x) {
    float r = rintf(x * 4096.0f);
    r = fminf(fmaxf(r, -32768.0f), 32767.0f);
    return r * (1.0f / 4096.0f);
}

// ---------------- prepass kernels ----------------
__global__ void zero_border_kernel() {
    int b = blockIdx.x;              // 32*58
    int n = b / HP_, hp = b % HP_;
    __half* rowp = g_xp + ((size_t)(n * HP_ + hp)) * WP_ * C_;
    uint4 z = make_uint4(0, 0, 0, 0);
    if (hp == 0 || hp == HP_ - 1) {
        for (int i = threadIdx.x; i < WP_ * C_ / 8; i += blockDim.x)
            reinterpret_cast<uint4*>(rowp)[i] = z;
    } else {
        if (threadIdx.x < 32) {
            int side = threadIdx.x >> 4;
            int q    = threadIdx.x & 15;
            __half* colp = rowp + (side ? (size_t)(WP_ - 1) * C_ : 0);
            reinterpret_cast<uint4*>(colp)[q] = z;
        }
    }
}

__global__ void xform_x_kernel(const float* __restrict__ x) {
    __shared__ __half st[W_ * C_];
    const int n = blockIdx.x, h = blockIdx.y;
    const int tid = threadIdx.x;
    const int c  = tid >> 1;
    const int wh = (tid & 1) * 28;
    const float* src = x + ((size_t)(n * C_ + c) * H_ + h) * W_ + wh;
    #pragma unroll
    for (int j = 0; j < 7; ++j) {
        float4 v = *reinterpret_cast<const float4*>(src + 4 * j);
        int wb = wh + 4 * j;
        st[(wb + 0) * C_ + c] = __float2half_rn(quant16f(v.x));
        st[(wb + 1) * C_ + c] = __float2half_rn(quant16f(v.y));
        st[(wb + 2) * C_ + c] = __float2half_rn(quant16f(v.z));
        st[(wb + 3) * C_ + c] = __float2half_rn(quant16f(v.w));
    }
    __syncthreads();
    __half* dst = g_xp + ((size_t)((n * HP_ + h + 1) * WP_ + 1)) * C_;
    for (int idx = tid; idx < W_ * C_ / 8; idx += 256) {
        int w = idx >> 4, q = idx & 15;
        reinterpret_cast<uint4*>(dst + (size_t)w * C_)[q] =
            reinterpret_cast<const uint4*>(st + w * C_)[q];
    }
}

__global__ void quant_w_kernel(const float* __restrict__ w) {
    int idx = blockIdx.x * 256 + threadIdx.x;
    if (idx >= K_ * KINP) return;
    int k = idx / KINP, t = idx % KINP;
    int rs = t >> 7, c = t & 127;
    float v = w[(size_t)(k * C_ + c) * 9 + rs];
    g_wq[idx] = __float2half_rn(quant16f(v));
}

// ---------------- main conv kernel: HMMA, 256 thr, 2 CTAs/SM ----------------
// grid (784, 2). CTA: 128 k-out x 128 pixels, K loop 18 x BK=64.
__global__ __launch_bounds__(256, 2) void conv_hmma_kernel(float* __restrict__ out) {
    extern __shared__ __align__(128) __half smem[];
    const uint32_t sbase = smem_u32(smem);

    const int tid  = threadIdx.x;
    const int lane = tid & 31;
    const int wid  = tid >> 5;          // 0..7
    const int warpM = wid & 3;          // 4 warps along M (32 rows each)
    const int warpN = wid >> 2;         // 2 warps along N (64 pixels each)
    const int g  = lane >> 2;
    const int tg = lane & 3;

    const int p0 = blockIdx.x * BN;
    const int k0 = blockIdx.y * BM;

    // ---- loader mapping: row = tid&127, 4 alternating 16B chunks ----
    const int ldRow  = tid & 127;
    const int ldHalf = tid >> 7;                     // 0 or 1
    const __half* aG = g_wq + (size_t)(k0 + ldRow) * KINP;
    const int bp  = p0 + ldRow;
    const int bn  = bp / HW_;
    const int bhw = bp % HW_;
    const int bh  = bhw / W_;
    const int bw  = bhw % W_;
    const __half* bG = g_xp + ((size_t)((bn * HP_ + bh) * WP_ + bw)) * C_;

    // ---- fragment ldmatrix base addresses ----
    const uint32_t fragSel = ((lane & 15) * PITCH + ((lane >> 4) << 3)) * 2;
    const uint32_t aFragBase = sbase + (uint32_t)(warpM * 32 * PITCH * 2) + fragSel;
    const uint32_t bFragBase = sbase + (uint32_t)SA_BYTES
                             + (uint32_t)(warpN * 64 * PITCH * 2) + fragSel;

    float acc[2][8][4];
    #pragma unroll
    for (int i = 0; i < 2; ++i)
        #pragma unroll
        for (int j = 0; j < 8; ++j)
            #pragma unroll
            for (int e = 0; e < 4; ++e) acc[i][j][e] = 0.0f;

    auto load_stage = [&](int s) {
        const int buf = s % 3;
        const uint32_t sA = sbase + buf * STAGE_BYTES;
        const uint32_t sB = sA + SA_BYTES;
        const int rs = s >> 1;
        const int r  = (rs * 11) >> 5;               // rs/3 for rs<9
        const int ss = rs - 3 * r;
        const int ch = (s & 1) << 6;
        const __half* asrc = aG + s * BK;
        const __half* bsrc = bG + (r * WP_ + ss) * C_ + ch;
        #pragma unroll
        for (int j = 0; j < 4; ++j) {
            const int c = 2 * j + ldHalf;
            CP16(sA + (ldRow * PITCH + c * 8) * 2, asrc + c * 8);
            CP16(sB + (ldRow * PITCH + c * 8) * 2, bsrc + c * 8);
        }
    };

    auto compute = [&](int buf) {
        const uint32_t off = buf * STAGE_BYTES;
        #pragma unroll
        for (int kk = 0; kk < 4; ++kk) {
            const uint32_t kcb = kk * 32;            // 16 halves = 32 bytes
            uint32_t a[2][4], b[8][2];
            #pragma unroll
            for (int i = 0; i < 2; ++i)
                LDSM_X4(a[i][0], a[i][1], a[i][2], a[i][3],
                        aFragBase + off + kcb + i * (16 * PITCH * 2));
            #pragma unroll
            for (int jj = 0; jj < 4; ++jj)
                LDSM_X4(b[2 * jj][0], b[2 * jj + 1][0], b[2 * jj][1], b[2 * jj + 1][1],
                        bFragBase + off + kcb + jj * (16 * PITCH * 2));
            #pragma unroll
            for (int i = 0; i < 2; ++i)
                #pragma unroll
                for (int j = 0; j < 8; ++j)
                    asm volatile(
                        "mma.sync.aligned.m16n8k16.row.col.f32.f16.f16.f32 "
                        "{%0,%1,%2,%3}, {%4,%5,%6,%7}, {%8,%9}, {%0,%1,%2,%3};\n"
                        : "+f"(acc[i][j][0]), "+f"(acc[i][j][1]),
                          "+f"(acc[i][j][2]), "+f"(acc[i][j][3])
                        : "r"(a[i][0]), "r"(a[i][1]), "r"(a[i][2]), "r"(a[i][3]),
                          "r"(b[j][0]), "r"(b[j][1]));
        }
    };

    // ---- 3-stage pipeline ----
    load_stage(0); CP_COMMIT();
    load_stage(1); CP_COMMIT();

    #pragma unroll 1
    for (int s = 0; s < NSTEP; ++s) {
        if (s < NSTEP - 1) { CP_WAIT1(); } else { CP_WAIT0(); }
        __syncthreads();                 // stage s visible; buf (s+2)%3 free
        if (s + 2 < NSTEP) { load_stage(s + 2); CP_COMMIT(); }
        compute(s % 3);
    }

    // ---- epilogue: registers -> gmem (NCHW) ----
    #pragma unroll
    for (int i = 0; i < 2; ++i) {
        const int kb = k0 + warpM * 32 + i * 16 + g;
        #pragma unroll
        for (int j = 0; j < 8; ++j) {
            const int pc = p0 + warpN * 64 + j * 8 + tg * 2;
            #pragma unroll
            for (int e = 0; e < 2; ++e) {
                const unsigned pe = (unsigned)(pc + e);
                const unsigned nn = pe / HW_;
                out[pe + (size_t)HW_ * (255u * nn + (unsigned)kb)]       = acc[i][j][e];
                out[pe + (size_t)HW_ * (255u * nn + (unsigned)(kb + 8))] = acc[i][j][2 + e];
            }
        }
    }
}

extern "C" void kernel_launch(void* const* d_in, const int* in_sizes, int n_in,
                              void* d_out, int out_size) {
    const float* x   = (const float*)d_in[0];   // (32,128,56,56) f32
    const float* wgt = (const float*)d_in[1];   // (256,128,3,3)  f32

    zero_border_kernel<<<N_ * HP_, 128>>>();
    xform_x_kernel<<<dim3(N_, H_), 256>>>(x);
    quant_w_kernel<<<(K_ * KINP + 255) / 256, 256>>>(wgt);

    static bool attr_set = false;
    if (!attr_set) {
        cudaFuncSetAttribute(conv_hmma_kernel,
                             cudaFuncAttributeMaxDynamicSharedMemorySize, SMEM_TOTAL);
        attr_set = true;
    }
    dim3 grid(PIX_ / BN, K_ / BM);              // (784, 2)
    conv_hmma_kernel<<<grid, 256, SMEM_TOTAL>>>((float*)d_out);
}